// round 1
// baseline (speedup 1.0000x reference)
#include <cuda_runtime.h>
#include <math_constants.h>

// Shapes (fixed by the problem)
#define B   32
#define H   8192
#define HO  4096
#define W   256
#define W4  64          // W / 4 (float4 lanes)
#define CH  32          // output rows per thread in pool kernel
#define CHUNKS      (HO / CH)          // 128
#define SUBS        4                  // chunks handled per block (tid/64)
#define CHUNKGROUPS (CHUNKS / SUBS)    // 32

// Per-batch min/max scratch, encoded as order-preserving uint32.
__device__ unsigned g_min[B];
__device__ unsigned g_max[B];

__device__ __forceinline__ unsigned enc_f(float f) {
    unsigned u = __float_as_uint(f);
    return (u & 0x80000000u) ? ~u : (u | 0x80000000u);
}
__device__ __forceinline__ float dec_f(unsigned e) {
    unsigned u = (e & 0x80000000u) ? (e ^ 0x80000000u) : ~e;
    return __uint_as_float(u);
}

__global__ void init_minmax_kernel() {
    int i = threadIdx.x;
    if (i < B) {
        g_min[i] = 0xFFFFFFFFu;  // +inf-ish in encoded space
        g_max[i] = 0x00000000u;  // -inf-ish in encoded space
    }
}

// K1: pool along H (k=3,s=2,pad=1), write pooled to d_out (un-normalized),
// reduce per-batch min/max of pooled values.
__global__ __launch_bounds__(256, 4)
void pool_kernel(const float4* __restrict__ x, float4* __restrict__ out) {
    const int b    = blockIdx.x;
    const int w4   = threadIdx.x & (W4 - 1);
    const int sub  = threadIdx.x >> 6;                 // 0..3
    const int chunk = blockIdx.y * SUBS + sub;         // 0..127
    const int h0   = chunk * CH;                       // first output row

    const float4* __restrict__ xb = x + (size_t)b * H * W4;
    float4* __restrict__ ob = out + (size_t)b * HO * W4;

    float4 prev;
    if (h0 == 0) {
        prev.x = prev.y = prev.z = prev.w = -CUDART_INF_F;  // top pad
    } else {
        prev = xb[(size_t)(2 * h0 - 1) * W4 + w4];
    }

    float mn =  CUDART_INF_F;
    float mx = -CUDART_INF_F;

    int hin = 2 * h0;
    #pragma unroll 8
    for (int i = 0; i < CH; i++) {
        float4 a = xb[(size_t)hin * W4 + w4];
        float4 c = xb[(size_t)(hin + 1) * W4 + w4];
        float4 p;
        p.x = fmaxf(fmaxf(a.x, c.x), prev.x);
        p.y = fmaxf(fmaxf(a.y, c.y), prev.y);
        p.z = fmaxf(fmaxf(a.z, c.z), prev.z);
        p.w = fmaxf(fmaxf(a.w, c.w), prev.w);
        ob[(size_t)(h0 + i) * W4 + w4] = p;
        mn = fminf(mn, fminf(fminf(p.x, p.y), fminf(p.z, p.w)));
        mx = fmaxf(mx, fmaxf(fmaxf(p.x, p.y), fmaxf(p.z, p.w)));
        prev = c;
        hin += 2;
    }

    // Warp reduce
    #pragma unroll
    for (int off = 16; off > 0; off >>= 1) {
        mn = fminf(mn, __shfl_xor_sync(0xFFFFFFFFu, mn, off));
        mx = fmaxf(mx, __shfl_xor_sync(0xFFFFFFFFu, mx, off));
    }

    // Block reduce across 8 warps
    __shared__ float s_mn[8], s_mx[8];
    const int lane = threadIdx.x & 31;
    const int wid  = threadIdx.x >> 5;
    if (lane == 0) { s_mn[wid] = mn; s_mx[wid] = mx; }
    __syncthreads();
    if (wid == 0) {
        mn = (lane < 8) ? s_mn[lane] :  CUDART_INF_F;
        mx = (lane < 8) ? s_mx[lane] : -CUDART_INF_F;
        #pragma unroll
        for (int off = 4; off > 0; off >>= 1) {
            mn = fminf(mn, __shfl_xor_sync(0xFFFFFFFFu, mn, off));
            mx = fmaxf(mx, __shfl_xor_sync(0xFFFFFFFFu, mx, off));
        }
        if (lane == 0) {
            atomicMin(&g_min[b], enc_f(mn));
            atomicMax(&g_max[b], enc_f(mx));
        }
    }
}

// K2: in-place normalize d_out with per-batch min/max.
__global__ __launch_bounds__(256)
void norm_kernel(float4* __restrict__ out) {
    const size_t n = (size_t)B * HO * W4;       // float4 elements
    const size_t stride = (size_t)gridDim.x * blockDim.x;
    for (size_t i = (size_t)blockIdx.x * blockDim.x + threadIdx.x; i < n; i += stride) {
        const int b = (int)(i >> 18);           // HO*W4 = 262144 = 2^18
        const float mn  = dec_f(__ldg(&g_min[b]));
        const float mx  = dec_f(__ldg(&g_max[b]));
        const float inv = 1.0f / (mx - mn);
        float4 v = out[i];
        v.x = (v.x - mn) * inv;
        v.y = (v.y - mn) * inv;
        v.z = (v.z - mn) * inv;
        v.w = (v.w - mn) * inv;
        out[i] = v;
    }
}

extern "C" void kernel_launch(void* const* d_in, const int* in_sizes, int n_in,
                              void* d_out, int out_size) {
    (void)in_sizes; (void)n_in; (void)out_size;
    const float4* x = (const float4*)d_in[0];
    float4* out = (float4*)d_out;

    init_minmax_kernel<<<1, 32>>>();

    dim3 grid1(B, CHUNKGROUPS);     // 32 x 32 = 1024 blocks
    pool_kernel<<<grid1, 256>>>(x, out);

    norm_kernel<<<148 * 16, 256>>>(out);
}